// round 9
// baseline (speedup 1.0000x reference)
#include <cuda_runtime.h>
#include <cuda_fp16.h>
#include <math.h>

// Problem constants
#define NG   16          // NUM_GRIDS
#define NIX  32          // IN_X
#define NIZ  32          // IN_Z
#define NOUT 64          // OUT
#define NB   512         // BATCH
#define NC   17          // NUM_GRIDS + 1
#define IJ   (NIX * NIZ)         // 1024
#define JSTRH (IJ * NOUT)        // 65536 halfs: jj -> jj+1 step in P2h
#define ISTRH (NC * JSTRH)       // ii -> ii+1 step in P2h

// Repacked parameter tensor in fp16: P2h[cell][ij][o]  (o contiguous)
__device__ __half g_P2h[NC * NC * IJ * NOUT];

// ---------------------------------------------------------------------------
// Repack v2 (round-8 proven, ~16.5us = byte floor): P[cell][o][ij] (fp32)
// -> P2h[cell][ij][o] (fp16). float4 loads, uint4 (8-half) stores.
// ---------------------------------------------------------------------------
__global__ __launch_bounds__(256) void repack_kernel(const float* __restrict__ P) {
    __shared__ float tile[NOUT * 33];         // 8448 B
    const int cell = blockIdx.x >> 5;         // 0..288
    const int ij0  = (blockIdx.x & 31) << 5;  // 0..992
    const int t    = threadIdx.x;

    const float* src = P     + cell * (NOUT * IJ) + ij0;
    __half*      dst = g_P2h + cell * (IJ * NOUT) + ij0 * NOUT;

#pragma unroll
    for (int p = 0; p < 2; ++p) {
        const int f = t + p * 256;
        const int o = f >> 3;                 // 0..63
        const int c = f & 7;                  // 0..7
        const float4 v = *reinterpret_cast<const float4*>(src + o * IJ + c * 4);
        float* tp = tile + o * 33 + c * 4;
        tp[0] = v.x; tp[1] = v.y; tp[2] = v.z; tp[3] = v.w;
    }
    __syncthreads();

    const int ij = t >> 3;                    // 0..31
    const int og = t & 7;                     // 0..7
    float v[8];
#pragma unroll
    for (int m = 0; m < 8; ++m)
        v[m] = tile[(og * 8 + m) * 33 + ij];
    __half2 h0 = __floats2half2_rn(v[0], v[1]);
    __half2 h1 = __floats2half2_rn(v[2], v[3]);
    __half2 h2 = __floats2half2_rn(v[4], v[5]);
    __half2 h3 = __floats2half2_rn(v[6], v[7]);
    uint4 q;
    q.x = *reinterpret_cast<unsigned*>(&h0);
    q.y = *reinterpret_cast<unsigned*>(&h1);
    q.z = *reinterpret_cast<unsigned*>(&h2);
    q.w = *reinterpret_cast<unsigned*>(&h3);
    *reinterpret_cast<uint4*>(dst + ij * NOUT + og * 8) = q;
}

__device__ __forceinline__ unsigned h2u(__half2 h) {
    return *reinterpret_cast<unsigned*>(&h);
}

// ---------------------------------------------------------------------------
// Gather: grid (NB), block 512, one batch per block; all blocks sweep the
// same ij order (cross-batch L1/L2 reuse -- proven). Per-cell base + packed
// half2 weights hoisted to smem. Inner loop: dual independent HFMA2
// accumulators per m (8 fp16 chains -> same ILP as the proven f32 version)
// over 2-cell windows, HADD2+cvt+FADD flush. ~34 instr/cell vs ~64.
// ---------------------------------------------------------------------------
__global__ __launch_bounds__(512) void gather_kernel(
    const float* __restrict__ x,
    const float* __restrict__ z,
    const float* __restrict__ borders,
    const float* __restrict__ invlen,
    float* __restrict__ out)
{
    const int b   = blockIdx.x;
    const int tid = threadIdx.x;

    __shared__ float s_dx[NIX];
    __shared__ float s_dz[NIZ];
    __shared__ int   s_ixw[NIX];     // bin * NC (pre-multiplied)
    __shared__ int   s_izw[NIZ];
    __shared__ int   s_base[IJ];     // 4 KB: cell base offset (half units)
    __shared__ uint4 s_w[IJ];        // 16 KB: 4 duplicated-half2 weights

    // Pass 0: per-row/col bin + fractional offset (laplace cdf binning)
    if (tid < 64) {
        const float v = (tid < 32) ? x[tid * NB + b] : z[(tid - 32) * NB + b];
        const float e = expf(-fabsf(v));
        const float cdf = (v > 0.0f) ? (1.0f - 0.5f * e) : (0.5f * e);
        int idx = (int)(cdf * (float)NG);
        idx = max(0, min(NG - 1, idx));
        const float d = (v - borders[idx]) * invlen[idx];
        if (tid < 32) { s_ixw[tid] = idx * NC;   s_dx[tid] = d; }
        else          { s_izw[tid - 32] = idx;   s_dz[tid - 32] = d; }
    }
    __syncthreads();

    // Pass 1: per-cell base + packed bilinear weights (2 cells per thread)
#pragma unroll
    for (int c = 0; c < IJ / 512; ++c) {
        const int ij = tid + c * 512;
        const int i = ij >> 5;
        const int j = ij & 31;
        const float dx = s_dx[i];
        const float dz = s_dz[j];
        const float ax = 1.0f - dx;
        const float az = 1.0f - dz;
        uint4 wp;
        wp.x = h2u(__float2half2_rn(ax * az));
        wp.y = h2u(__float2half2_rn(ax * dz));
        wp.z = h2u(__float2half2_rn(dx * az));
        wp.w = h2u(__float2half2_rn(dx * dz));
        s_w[ij] = wp;
        s_base[ij] = ((s_ixw[i] + s_izw[j]) * IJ + ij) * NOUT;
    }
    __syncthreads();

    const int og  = tid & 7;        // o-group: halfs [og*8, og*8+8) of 64
    const int ijg = tid >> 3;       // ij-group 0..63
    const int ooff = og * 8;

    float acc[8];
#pragma unroll
    for (int e = 0; e < 8; ++e) acc[e] = 0.0f;

#pragma unroll 2
    for (int ko = 0; ko < 8; ++ko) {          // 8 windows of 2 cells
        __half2 u[4], vv[4];
#pragma unroll
        for (int m = 0; m < 4; ++m) {
            u[m]  = __float2half2_rn(0.0f);
            vv[m] = __float2half2_rn(0.0f);
        }

#pragma unroll
        for (int ki = 0; ki < 2; ++ki) {
            const int ij = ijg + (((ko << 1) + ki) << 6);
            const int base = s_base[ij] + ooff;
            const uint4 wq = s_w[ij];
            const __half* p = g_P2h + base;

            const uint4 q00 = *reinterpret_cast<const uint4*>(p);
            const uint4 q01 = *reinterpret_cast<const uint4*>(p + JSTRH);
            const uint4 q10 = *reinterpret_cast<const uint4*>(p + ISTRH);
            const uint4 q11 = *reinterpret_cast<const uint4*>(p + ISTRH + JSTRH);

            const __half2 w00 = *reinterpret_cast<const __half2*>(&wq.x);
            const __half2 w01 = *reinterpret_cast<const __half2*>(&wq.y);
            const __half2 w10 = *reinterpret_cast<const __half2*>(&wq.z);
            const __half2 w11 = *reinterpret_cast<const __half2*>(&wq.w);

            const __half2* h00 = reinterpret_cast<const __half2*>(&q00);
            const __half2* h01 = reinterpret_cast<const __half2*>(&q01);
            const __half2* h10 = reinterpret_cast<const __half2*>(&q10);
            const __half2* h11 = reinterpret_cast<const __half2*>(&q11);
#pragma unroll
            for (int m = 0; m < 4; ++m) {
                u[m]  = __hfma2(h00[m], w00, u[m]);    // chain A: corners 00,10
                vv[m] = __hfma2(h01[m], w01, vv[m]);   // chain B: corners 01,11
                u[m]  = __hfma2(h10[m], w10, u[m]);
                vv[m] = __hfma2(h11[m], w11, vv[m]);
            }
        }
        // Flush: merge chains, convert, accumulate in f32
#pragma unroll
        for (int m = 0; m < 4; ++m) {
            const float2 f = __half22float2(__hadd2(u[m], vv[m]));
            acc[2 * m + 0] += f.x;
            acc[2 * m + 1] += f.y;
        }
    }

    // Warp reduction over the 4 ij-groups per warp (lane = (ijg&3)*8 + og)
#pragma unroll
    for (int m = 8; m <= 16; m <<= 1)
#pragma unroll
        for (int e = 0; e < 8; ++e)
            acc[e] += __shfl_xor_sync(0xffffffffu, acc[e], m);

    // Cross-warp reduction: 16 warps x 8 o-groups x 8 elems
    __shared__ float s_part[16][8][8];
    const int warp = tid >> 5;
    const int lane = tid & 31;
    if (lane < 8) {
#pragma unroll
        for (int e = 0; e < 8; ++e) s_part[warp][lane][e] = acc[e];
    }
    __syncthreads();

    if (tid < 64) {
        const int og2 = tid >> 3;       // o-group
        const int e   = tid & 7;        // element within group
        float a = s_part[0][og2][e];
#pragma unroll
        for (int w = 1; w < 16; ++w) a += s_part[w][og2][e];
        out[(og2 * 8 + e) * NB + b] = a;
    }
}

// ---------------------------------------------------------------------------
extern "C" void kernel_launch(void* const* d_in, const int* in_sizes, int n_in,
                              void* d_out, int out_size) {
    const float* x       = (const float*)d_in[0];  // (32, 512)
    const float* z       = (const float*)d_in[1];  // (32, 512)
    const float* P       = (const float*)d_in[2];  // (17,17,64,32,32)
    const float* borders = (const float*)d_in[3];  // (17,)
    const float* invlen  = (const float*)d_in[4];  // (16,)
    float* out = (float*)d_out;                    // (64, 512)

    (void)in_sizes; (void)n_in; (void)out_size;

    // Phase 1: repack P -> P2h (fp16, o contiguous), vectorized
    {
        repack_kernel<<<NC * NC * 32, 256>>>(P);   // 9248 blocks
    }

    // Phase 2: gather + accumulate (HFMA2 dual-chain inner loop)
    {
        gather_kernel<<<NB, 512>>>(x, z, borders, invlen, out);
    }
}